// round 15
// baseline (speedup 1.0000x reference)
#include <cuda_runtime.h>
#include <cuda_bf16.h>
#include <cstdint>

// Problem constants
#define BB   2
#define CH   128
#define HWN  4096
#define NTOK 4096
#define BNC  8192          // BB * NTOK
#define CC   256           // 2*CH (real plane then imag plane)
#define NN   (4096ull*4096ull)
#define EPSV 1e-5f
#define SCALE_QK 0.08838834764831845f   // 1/sqrt(128)

typedef __nv_bfloat16 bf16;

// ---------------- scratch (device globals) ---------------------------------
__device__ __align__(256) bf16   g_xt  [(size_t)BNC * CC];   // normalized token-major bf16
__device__ __align__(256) bf16   g_qt  [(size_t)BNC * CC];   // Q token-major bf16 (pre-scaled)
__device__ __align__(256) bf16   g_kt  [(size_t)BNC * CC];   // K token-major bf16
__device__ __align__(256) bf16   g_vp  [(size_t)CC * BNC];   // V planar bf16 (cc, B*N)
__device__ __align__(256) bf16   g_attn[(size_t)BB * NN];    // P = exp(logits), bf16 (64MB)
__device__ __align__(256) bf16   g_o   [(size_t)BB * NTOK * CC]; // partial out, K-half 0 (bf16)
__device__ __align__(256) bf16   g_o2  [(size_t)BB * NTOK * CC]; // partial out, K-half 1 (bf16)
__device__ __align__(256) float  g_rs  [(size_t)BB * NTOK];  // row sums of exp
__device__ __align__(256) bf16   g_ws_bf[3 * CC * CC];       // stacked complex weights bf16
__device__ float g_bs  [3 * CC];
__device__ float g_scale[CC];
__device__ float g_shift[CC];

// ---------------- PTX helpers (base-ISA only) --------------------------------
__device__ __forceinline__ uint32_t smem_u32(const void* p) {
    uint32_t a;
    asm("{ .reg .u64 t; cvta.to.shared.u64 t, %1; cvt.u32.u64 %0, t; }" : "=r"(a) : "l"(p));
    return a;
}
__device__ __forceinline__ void cpa16(uint32_t dst, const void* src) {
    asm volatile("cp.async.cg.shared.global [%0], [%1], 16;" :: "r"(dst), "l"(src) : "memory");
}
#define CP_COMMIT() asm volatile("cp.async.commit_group;" ::: "memory")
#define CP_WAIT(n)  asm volatile("cp.async.wait_group %0;" :: "n"(n) : "memory")

#define LDMX4(r, addr) \
    asm volatile("ldmatrix.sync.aligned.m8n8.x4.shared.b16 {%0,%1,%2,%3}, [%4];" \
        : "=r"((r)[0]), "=r"((r)[1]), "=r"((r)[2]), "=r"((r)[3]) : "r"(addr))

#define MMA16816(d, a, b0v, b1v) \
    asm volatile("mma.sync.aligned.m16n8k16.row.col.f32.bf16.bf16.f32 " \
        "{%0,%1,%2,%3}, {%4,%5,%6,%7}, {%8,%9}, {%0,%1,%2,%3};" \
        : "+f"((d)[0]), "+f"((d)[1]), "+f"((d)[2]), "+f"((d)[3]) \
        : "r"((a)[0]), "r"((a)[1]), "r"((a)[2]), "r"((a)[3]), "r"(b0v), "r"(b1v))

// SMEM tile geometry: 128 rows x 64 bf16 (128B data) padded to 144B/row.
#define ROWB   144
#define TILEB  (128 * ROWB)          // 18432 B
#define STAGES 3
#define SM_TOTAL (2 * STAGES * TILEB) // 110592 B

// Epilogue staging tile: 128 x 128 bf16, pitch 136 bf16 (272B).
#define SPITCH 136

// ---------------- unified HMMA GEMM: D(128x128) = A(128xK) . B(128xK)^T ----
// R11-proven mainloop: 256 thr = 8 warps (4M x 2N), warp tile 32x64, 3-stage,
// single __syncthreads per K-chunk. Staged, coalesced epilogues.
// EPI 0: proj QK (grid 64 x 4)        A=g_xt,   B=g_ws_bf[0..3], K=256
// EPI 1: logit (grid 32 x 34 x 2):
//          by <  32 -> logits         A=g_qt,   B=g_kt,          K=256 (P=exp, rowsums)
//          by >= 32 -> V-projection   A=g_xt,   B=g_ws_bf[4..5], K=256 (wave filler)
// EPI 2: out   (grid 32 x 2 x 4)      A=P bf16, B=g_vp,          K=2048 (split-K=2)
template <int EPI>
__global__ __launch_bounds__(256, 2) void gemm_kernel() {
    extern __shared__ __align__(16) char smem[];
    const int tid = threadIdx.x, lane = tid & 31, wid = tid >> 5;
    const int bx = blockIdx.x, by = blockIdx.y, bz = blockIdx.z;

    const bf16 *Ap, *Bp; size_t lda, ldb; int nk;
    bool vpath = false; int vx = 0, vb = 0;
    if (EPI == 0) {
        Ap = g_xt + (size_t)bx * 128 * CC;                 lda = CC;
        Bp = g_ws_bf + (size_t)by * 128 * CC;              ldb = CC;   nk = 4;
    } else if (EPI == 1) {
        if (by < 32) {
            Ap = g_qt + ((size_t)bz * NTOK + bx * 128) * CC;   lda = CC;
            Bp = g_kt + ((size_t)bz * NTOK + by * 128) * CC;   ldb = CC;  nk = 4;
        } else {                                   // V-projection filler CTAs
            vpath = true;
            int t = (by - 32) * 64 + bz * 32 + bx; // 0..127
            vb = t >> 6;                           // 0..1 (cc half)
            vx = t & 63;                           // 0..63 (token tile over B*N)
            Ap = g_xt + (size_t)vx * 128 * CC;              lda = CC;
            Bp = g_ws_bf + (size_t)(4 + vb) * 128 * CC;     ldb = CC;  nk = 4;
        }
    } else {
        const int b = bz >> 1, ks = bz & 1;
        Ap = g_attn + ((size_t)b * NTOK + bx * 128) * NTOK + ks * 2048;
        lda = NTOK;
        Bp = g_vp + (size_t)(by * 128) * BNC + (size_t)b * NTOK + ks * 2048;
        ldb = BNC;  nk = 32;
    }

    const uint32_t sa0 = smem_u32(smem);
    const uint32_t sb0 = sa0 + STAGES * TILEB;

    auto load_tile = [&](int i) {
        const int kk0 = i * 64;
        const int st = i % STAGES;
        const uint32_t ab = sa0 + st * TILEB;
        const uint32_t bb = sb0 + st * TILEB;
        #pragma unroll
        for (int it = 0; it < 4; it++) {
            int l = tid + it * 256;
            int row = l >> 3, kc = l & 7;
            cpa16(ab + row * ROWB + kc * 16, Ap + (size_t)row * lda + kk0 + kc * 8);
            cpa16(bb + row * ROWB + kc * 16, Bp + (size_t)row * ldb + kk0 + kc * 8);
        }
    };

    float acc[2][8][4];
    #pragma unroll
    for (int mt = 0; mt < 2; mt++)
        #pragma unroll
        for (int nj = 0; nj < 8; nj++)
            #pragma unroll
            for (int e = 0; e < 4; e++) acc[mt][nj][e] = 0.f;

    const int m0  = (wid & 3) * 32;
    const int n0w = (wid >> 2) * 64;

    load_tile(0); CP_COMMIT();
    load_tile(1); CP_COMMIT();

    for (int i = 0; i < nk; i++) {
        if (i + 1 < nk) { CP_WAIT(1); }
        else            { CP_WAIT(0); }
        __syncthreads();
        if (i + 2 < nk) { load_tile(i + 2); CP_COMMIT(); }

        const int st = i % STAGES;
        const uint32_t aB = sa0 + st * TILEB;
        const uint32_t bB = sb0 + st * TILEB;
        #pragma unroll
        for (int ks = 0; ks < 64; ks += 16) {
            uint32_t af[2][4], bfr[4][4];
            #pragma unroll
            for (int mt = 0; mt < 2; mt++) {
                uint32_t addr = aB + (m0 + mt * 16 + (lane & 15)) * ROWB
                              + (ks + ((lane >> 4) << 3)) * 2;
                LDMX4(af[mt], addr);
            }
            #pragma unroll
            for (int nt = 0; nt < 4; nt++) {
                uint32_t addr = bB + (n0w + nt * 16 + (lane & 7) + ((lane & 16) >> 1)) * ROWB
                              + (ks + (((lane >> 3) & 1) << 3)) * 2;
                LDMX4(bfr[nt], addr);
            }
            #pragma unroll
            for (int mt = 0; mt < 2; mt++)
                #pragma unroll
                for (int nt = 0; nt < 4; nt++) {
                    MMA16816(acc[mt][2 * nt],     af[mt], bfr[nt][0], bfr[nt][1]);
                    MMA16816(acc[mt][2 * nt + 1], af[mt], bfr[nt][2], bfr[nt][3]);
                }
        }
    }

    // ---- epilogue: process + stage into smem ----
    __syncthreads();
    bf16* sd = (bf16*)smem;
    const int lr_base = m0 + (lane >> 2);
    const int c_loc0 = n0w + (lane & 3) * 2;
    float sumA[2] = {0.f, 0.f};
    float sumB[2] = {0.f, 0.f};

    #pragma unroll
    for (int mt = 0; mt < 2; mt++) {
        #pragma unroll
        for (int nj = 0; nj < 8; nj++) {
            float* d = acc[mt][nj];
            const int lr0 = lr_base + mt * 16;
            const int c   = c_loc0 + nj * 8;
            float p00, p01, p10, p11;

            if (EPI == 0) {
                int gc = by * 128 + c;               // 0..511 (Q or K)
                float bi0 = g_bs[gc], bi1 = g_bs[gc + 1];
                if (gc < 256) {
                    p00 = (d[0] + bi0) * SCALE_QK; p01 = (d[1] + bi1) * SCALE_QK;
                    p10 = (d[2] + bi0) * SCALE_QK; p11 = (d[3] + bi1) * SCALE_QK;
                } else {
                    p00 = d[0] + bi0; p01 = d[1] + bi1;
                    p10 = d[2] + bi0; p11 = d[3] + bi1;
                }
            } else if (EPI == 1) {
                if (!vpath) {
                    // P = exp(logit) (no max subtraction; bounded, fp32/bf16 safe)
                    p00 = __expf(d[0]); p01 = __expf(d[1]);
                    p10 = __expf(d[2]); p11 = __expf(d[3]);
                    sumA[mt] += p00 + p01;
                    sumB[mt] += p10 + p11;
                } else {
                    int gc = 512 + vb * 128 + c;     // V bias
                    float bi0 = g_bs[gc], bi1 = g_bs[gc + 1];
                    p00 = d[0] + bi0; p01 = d[1] + bi1;
                    p10 = d[2] + bi0; p11 = d[3] + bi1;
                }
            } else {
                p00 = d[0]; p01 = d[1]; p10 = d[2]; p11 = d[3];
            }

            if (!vpath) {
                *(__nv_bfloat162*)&sd[lr0 * SPITCH + c] =
                    __float22bfloat162_rn(make_float2(p00, p01));
                *(__nv_bfloat162*)&sd[(lr0 + 8) * SPITCH + c] =
                    __float22bfloat162_rn(make_float2(p10, p11));
            } else {                       // V: stage transposed (cc-major rows)
                sd[c * SPITCH + lr0]           = __float2bfloat16(p00);
                sd[(c + 1) * SPITCH + lr0]     = __float2bfloat16(p01);
                sd[c * SPITCH + lr0 + 8]       = __float2bfloat16(p10);
                sd[(c + 1) * SPITCH + lr0 + 8] = __float2bfloat16(p11);
            }
        }
    }

    if (EPI == 1 && !vpath) {
        #pragma unroll
        for (int mt = 0; mt < 2; mt++) {
            float sA = sumA[mt], sB = sumB[mt];
            sA += __shfl_xor_sync(0xFFFFFFFF, sA, 1);
            sA += __shfl_xor_sync(0xFFFFFFFF, sA, 2);
            sB += __shfl_xor_sync(0xFFFFFFFF, sB, 1);
            sB += __shfl_xor_sync(0xFFFFFFFF, sB, 2);
            if ((lane & 3) == 0) {
                int row = bx * 128 + lr_base + mt * 16;
                atomicAdd(&g_rs[(size_t)bz * NTOK + row], sA);
                atomicAdd(&g_rs[(size_t)bz * NTOK + row + 8], sB);
            }
        }
    }
    __syncthreads();

    // ---- coalesced write-out: 128 rows x 256B, 16B per thread-iteration ----
    #pragma unroll
    for (int it = tid; it < 2048; it += 256) {
        int row = it >> 4;
        int ch  = (it & 15) * 8;
        uint4 v = *(uint4*)&sd[row * SPITCH + ch];
        if (EPI == 0) {
            if (by < 2)
                *(uint4*)&g_qt[(size_t)(bx * 128 + row) * CC + (by & 1) * 128 + ch] = v;
            else
                *(uint4*)&g_kt[(size_t)(bx * 128 + row) * CC + ((by - 2) & 1) * 128 + ch] = v;
        } else if (EPI == 1) {
            if (!vpath) {
                bf16* L = g_attn + (size_t)bz * NN;
                *(uint4*)&L[(size_t)(bx * 128 + row) * NTOK + by * 128 + ch] = v;
            } else {
                *(uint4*)&g_vp[(size_t)(vb * 128 + row) * BNC + vx * 128 + ch] = v;
            }
        } else {
            const int b = bz >> 1, ks = bz & 1;
            bf16* O = (ks ? g_o2 : g_o) + (size_t)b * NTOK * CC;
            *(uint4*)&O[(size_t)(bx * 128 + row) * CC + by * 128 + ch] = v;
        }
    }
}

// ---------------- prep: BN stats (blocks 0..127) + weight stacking + zero ---
__global__ __launch_bounds__(256) void prep_kernel(
    const float* __restrict__ x,
    const float* __restrict__ bn_w, const float* __restrict__ bn_b,
    const float* __restrict__ wq, const float* __restrict__ bq,
    const float* __restrict__ wk, const float* __restrict__ bk,
    const float* __restrict__ wv, const float* __restrict__ bv) {
    if (blockIdx.x < CH) {
        int c = blockIdx.x;
        float sr = 0.f, si = 0.f, qr = 0.f, qi = 0.f;
        #pragma unroll
        for (int b = 0; b < BB; b++) {
            const float4* p = (const float4*)x + (size_t)(b * CH + c) * (HWN / 2);
            for (int i = threadIdx.x; i < HWN / 2; i += 256) {
                float4 v = p[i];
                sr += v.x + v.z;  si += v.y + v.w;
                qr += v.x * v.x + v.z * v.z;
                qi += v.y * v.y + v.w * v.w;
            }
        }
        #pragma unroll
        for (int o = 16; o > 0; o >>= 1) {
            sr += __shfl_xor_sync(0xFFFFFFFF, sr, o);
            si += __shfl_xor_sync(0xFFFFFFFF, si, o);
            qr += __shfl_xor_sync(0xFFFFFFFF, qr, o);
            qi += __shfl_xor_sync(0xFFFFFFFF, qi, o);
        }
        __shared__ float s4[4][8];
        int wid = threadIdx.x >> 5, lane = threadIdx.x & 31;
        if (lane == 0) { s4[0][wid] = sr; s4[1][wid] = si; s4[2][wid] = qr; s4[3][wid] = qi; }
        __syncthreads();
        if (threadIdx.x == 0) {
            float tsr = 0, tsi = 0, tqr = 0, tqi = 0;
            #pragma unroll
            for (int w = 0; w < 8; w++) { tsr += s4[0][w]; tsi += s4[1][w]; tqr += s4[2][w]; tqi += s4[3][w]; }
            const float inv = 1.f / (float)(BB * HWN);
            float mr = tsr * inv, mi = tsi * inv;
            float vr = tqr * inv - mr * mr, vi = tqi * inv - mi * mi;
            float scr = bn_w[c * 2 + 0] * rsqrtf(vr + EPSV);
            float sci = bn_w[c * 2 + 1] * rsqrtf(vi + EPSV);
            g_scale[c]      = scr;  g_shift[c]      = bn_b[c * 2 + 0] - mr * scr;
            g_scale[CH + c] = sci;  g_shift[CH + c] = bn_b[c * 2 + 1] - mi * sci;
        }
    } else {
        int idx = (blockIdx.x - CH) * 256 + threadIdx.x;   // 0 .. 3*128*128-1
        int p = idx / (CH * CH);
        int r = idx - p * (CH * CH);
        int o = r / CH, i = r % CH;
        const float* w = (p == 0) ? wq : ((p == 1) ? wk : wv);
        float wr = w[(o * CH + i) * 2 + 0];
        float wi = w[(o * CH + i) * 2 + 1];
        bf16* ws = g_ws_bf + (size_t)p * CC * CC;
        ws[o * CC + i]             = __float2bfloat16( wr);
        ws[o * CC + CH + i]        = __float2bfloat16(-wi);
        ws[(CH + o) * CC + i]      = __float2bfloat16( wi);
        ws[(CH + o) * CC + CH + i] = __float2bfloat16( wr);
        if (i == 0) {
            const float* bbp = (p == 0) ? bq : ((p == 1) ? bk : bv);
            g_bs[p * CC + o]      = bbp[o * 2 + 0];
            g_bs[p * CC + CH + o] = bbp[o * 2 + 1];
        }
        int zb = blockIdx.x - CH;
        if (zb < 32) g_rs[zb * 256 + threadIdx.x] = 0.f;
    }
}

// ---------------- normalize: token-major bf16 only ---------------------------
__global__ void normalize_kernel(const float* __restrict__ x) {
    __shared__ float shr[32][33];
    __shared__ float shi[32][33];
    int b  = blockIdx.z;
    int c0 = blockIdx.y * 32;
    int n0 = blockIdx.x * 32;
    int tx = threadIdx.x, ty = threadIdx.y;
    int c = c0 + ty, n = n0 + tx;
    float2 v = ((const float2*)x)[(size_t)(b * CH + c) * HWN + n];
    shr[ty][tx] = v.x * g_scale[c]      + g_shift[c];
    shi[ty][tx] = v.y * g_scale[CH + c] + g_shift[CH + c];
    __syncthreads();
    int token = n0 + ty;
    int cw = c0 + (tx & 15) * 2;
    bf16* dst = g_xt + ((size_t)b * NTOK + token) * CC;
    if (tx < 16) {
        *(__nv_bfloat162*)&dst[cw] =
            __float22bfloat162_rn(make_float2(shr[(tx & 15) * 2][ty], shr[(tx & 15) * 2 + 1][ty]));
    } else {
        *(__nv_bfloat162*)&dst[CH + cw] =
            __float22bfloat162_rn(make_float2(shi[(tx & 15) * 2][ty], shi[(tx & 15) * 2 + 1][ty]));
    }
}

// ---------------- residual add (xn recomputed) + rowsum norm + split-K ------
__global__ void final_add_kernel(const float* __restrict__ x,
                                 const float* __restrict__ gamma_p,
                                 float* __restrict__ out) {
    __shared__ float shr[32][33];
    __shared__ float shi[32][33];
    float gamma = *gamma_p;
    int b  = blockIdx.z;
    int c0 = blockIdx.y * 32;
    int n0 = blockIdx.x * 32;
    int tx = threadIdx.x, ty = threadIdx.y;
    size_t obase = ((size_t)b * NTOK + n0 + ty) * CC;
    {
        float pr = __bfloat162float(g_o [obase + c0 + tx]) +
                   __bfloat162float(g_o2[obase + c0 + tx]);
        float pi = __bfloat162float(g_o [obase + CH + c0 + tx]) +
                   __bfloat162float(g_o2[obase + CH + c0 + tx]);
        shr[ty][tx] = pr; shi[ty][tx] = pi;
    }
    __syncthreads();
    int c = c0 + ty;
    int n = n0 + tx;
    size_t col = (size_t)b * NTOK + n;
    float inv = gamma / g_rs[col];
    size_t oi = (size_t)(b * CH + c) * HWN + n;
    float2 xv = ((const float2*)x)[oi];
    float xr = xv.x * g_scale[c]      + g_shift[c];
    float xi = xv.y * g_scale[CH + c] + g_shift[CH + c];
    float2 ov;
    ov.x = xr + inv * shr[tx][ty];
    ov.y = xi + inv * shi[tx][ty];
    ((float2*)out)[oi] = ov;
}

// ---------------- launch -----------------------------------------------------
extern "C" void kernel_launch(void* const* d_in, const int* in_sizes, int n_in,
                              void* d_out, int out_size) {
    const float* x    = (const float*)d_in[0];
    const float* bn_w = (const float*)d_in[1];
    const float* bn_b = (const float*)d_in[2];
    const float* wq   = (const float*)d_in[3];
    const float* bq   = (const float*)d_in[4];
    const float* wk   = (const float*)d_in[5];
    const float* bk   = (const float*)d_in[6];
    const float* wv   = (const float*)d_in[7];
    const float* bv   = (const float*)d_in[8];
    const float* gam  = (const float*)d_in[9];
    float* out = (float*)d_out;

    static int attr_set = 0;
    if (!attr_set) {
        cudaFuncSetAttribute(gemm_kernel<0>, cudaFuncAttributeMaxDynamicSharedMemorySize, SM_TOTAL);
        cudaFuncSetAttribute(gemm_kernel<1>, cudaFuncAttributeMaxDynamicSharedMemorySize, SM_TOTAL);
        cudaFuncSetAttribute(gemm_kernel<2>, cudaFuncAttributeMaxDynamicSharedMemorySize, SM_TOTAL);
        attr_set = 1;
    }

    prep_kernel<<<CH + 192, 256>>>(x, bn_w, bn_b, wq, bq, wk, bk, wv, bv);
    normalize_kernel<<<dim3(HWN / 32, CH / 32, BB), dim3(32, 32)>>>(x);
    gemm_kernel<0><<<dim3(BNC / 128, 4), 256, SM_TOTAL>>>();                    // QK proj
    gemm_kernel<1><<<dim3(NTOK / 128, 34, BB), 256, SM_TOTAL>>>();              // logits + V-proj filler
    gemm_kernel<2><<<dim3(NTOK / 128, CC / 128, BB * 2), 256, SM_TOTAL>>>();
    final_add_kernel<<<dim3(HWN / 32, CH / 32, BB), dim3(32, 32)>>>(x, gam, out);
}

// round 16
// speedup vs baseline: 1.0154x; 1.0154x over previous
#include <cuda_runtime.h>
#include <cuda_bf16.h>
#include <cstdint>

// Problem constants
#define BB   2
#define CH   128
#define HWN  4096
#define NTOK 4096
#define BNC  8192          // BB * NTOK
#define CC   256           // 2*CH (real plane then imag plane)
#define NN   (4096ull*4096ull)
#define EPSV 1e-5f
#define SCALE_QK 0.08838834764831845f   // 1/sqrt(128)

typedef __nv_bfloat16 bf16;

// ---------------- scratch (device globals) ---------------------------------
__device__ __align__(256) bf16   g_xt  [(size_t)BNC * CC];   // normalized token-major bf16
__device__ __align__(256) bf16   g_qt  [(size_t)BNC * CC];   // Q token-major bf16 (pre-scaled)
__device__ __align__(256) bf16   g_kt  [(size_t)BNC * CC];   // K token-major bf16
__device__ __align__(256) bf16   g_vp  [(size_t)CC * BNC];   // V planar bf16 (cc, B*N)
__device__ __align__(256) bf16   g_attn[(size_t)BB * NN];    // P = exp(logits), bf16 (64MB)
__device__ __align__(256) bf16   g_o   [(size_t)BB * NTOK * CC]; // partial out, K-half 0 (bf16)
__device__ __align__(256) bf16   g_o2  [(size_t)BB * NTOK * CC]; // partial out, K-half 1 (bf16)
__device__ __align__(256) float  g_rs  [(size_t)BB * NTOK];  // row sums of exp
__device__ __align__(256) bf16   g_ws_bf[3 * CC * CC];       // stacked complex weights bf16
__device__ float g_bs  [3 * CC];
__device__ float g_scale[CC];
__device__ float g_shift[CC];

// ---------------- PTX helpers (base-ISA only) --------------------------------
__device__ __forceinline__ uint32_t smem_u32(const void* p) {
    uint32_t a;
    asm("{ .reg .u64 t; cvta.to.shared.u64 t, %1; cvt.u32.u64 %0, t; }" : "=r"(a) : "l"(p));
    return a;
}
__device__ __forceinline__ void cpa16(uint32_t dst, const void* src) {
    asm volatile("cp.async.cg.shared.global [%0], [%1], 16;" :: "r"(dst), "l"(src) : "memory");
}
#define CP_COMMIT() asm volatile("cp.async.commit_group;" ::: "memory")
#define CP_WAIT(n)  asm volatile("cp.async.wait_group %0;" :: "n"(n) : "memory")

#define LDMX4(r, addr) \
    asm volatile("ldmatrix.sync.aligned.m8n8.x4.shared.b16 {%0,%1,%2,%3}, [%4];" \
        : "=r"((r)[0]), "=r"((r)[1]), "=r"((r)[2]), "=r"((r)[3]) : "r"(addr))

#define MMA16816(d, a, b0v, b1v) \
    asm volatile("mma.sync.aligned.m16n8k16.row.col.f32.bf16.bf16.f32 " \
        "{%0,%1,%2,%3}, {%4,%5,%6,%7}, {%8,%9}, {%0,%1,%2,%3};" \
        : "+f"((d)[0]), "+f"((d)[1]), "+f"((d)[2]), "+f"((d)[3]) \
        : "r"((a)[0]), "r"((a)[1]), "r"((a)[2]), "r"((a)[3]), "r"(b0v), "r"(b1v))

// SMEM tile geometry: 128 rows x 64 bf16 (128B data) padded to 144B/row.
#define ROWB   144
#define TILEB  (128 * ROWB)          // 18432 B
#define STAGES 3
#define SM_TOTAL (2 * STAGES * TILEB) // 110592 B

// Epilogue staging tile: 128 x 128 bf16, pitch 136 bf16 (272B).
#define SPITCH 136

// ---------------- unified HMMA GEMM: D(128x128) = A(128xK) . B(128xK)^T ----
// R14-proven config: 256 thr = 8 warps (4M x 2N), warp tile 32x64, 3-stage,
// single __syncthreads per K-chunk, staged coalesced epilogues.
// NK is compile-time: nk=4 loops fully unroll (no modulo / stage arithmetic).
// EPI 0: proj  (grid 64 x 6)          A=g_xt,      B=g_ws_bf,  NK=4
// EPI 1: logit (grid 32 x 32 x 2)     A=g_qt,      B=g_kt,     NK=4  (P=exp, rowsums)
// EPI 2: out   (grid 32 x 2 x 4)      A=P bf16,    B=g_vp,     NK=32 (split-K=2)
template <int EPI, int NK>
__global__ __launch_bounds__(256, 2) void gemm_kernel() {
    extern __shared__ __align__(16) char smem[];
    const int tid = threadIdx.x, lane = tid & 31, wid = tid >> 5;
    const int bx = blockIdx.x, by = blockIdx.y, bz = blockIdx.z;

    const bf16 *Ap, *Bp; size_t lda, ldb;
    if (EPI == 0) {
        Ap = g_xt + (size_t)bx * 128 * CC;                 lda = CC;
        Bp = g_ws_bf + (size_t)by * 128 * CC;              ldb = CC;
    } else if (EPI == 1) {
        Ap = g_qt + ((size_t)bz * NTOK + bx * 128) * CC;   lda = CC;
        Bp = g_kt + ((size_t)bz * NTOK + by * 128) * CC;   ldb = CC;
    } else {
        const int b = bz >> 1, ks = bz & 1;
        Ap = g_attn + ((size_t)b * NTOK + bx * 128) * NTOK + ks * 2048;
        lda = NTOK;
        Bp = g_vp + (size_t)(by * 128) * BNC + (size_t)b * NTOK + ks * 2048;
        ldb = BNC;
    }

    const uint32_t sa0 = smem_u32(smem);
    const uint32_t sb0 = sa0 + STAGES * TILEB;

    auto load_tile = [&](int i) {
        const int kk0 = i * 64;
        const int st = i % STAGES;
        const uint32_t ab = sa0 + st * TILEB;
        const uint32_t bb = sb0 + st * TILEB;
        #pragma unroll
        for (int it = 0; it < 4; it++) {
            int l = tid + it * 256;
            int row = l >> 3, kc = l & 7;
            cpa16(ab + row * ROWB + kc * 16, Ap + (size_t)row * lda + kk0 + kc * 8);
            cpa16(bb + row * ROWB + kc * 16, Bp + (size_t)row * ldb + kk0 + kc * 8);
        }
    };

    float acc[2][8][4];
    #pragma unroll
    for (int mt = 0; mt < 2; mt++)
        #pragma unroll
        for (int nj = 0; nj < 8; nj++)
            #pragma unroll
            for (int e = 0; e < 4; e++) acc[mt][nj][e] = 0.f;

    const int m0  = (wid & 3) * 32;
    const int n0w = (wid >> 2) * 64;

    load_tile(0); CP_COMMIT();
    load_tile(1); CP_COMMIT();

    #pragma unroll 4
    for (int i = 0; i < NK; i++) {
        if (i + 1 < NK) { CP_WAIT(1); }
        else            { CP_WAIT(0); }
        __syncthreads();
        if (i + 2 < NK) { load_tile(i + 2); CP_COMMIT(); }

        const int st = i % STAGES;
        const uint32_t aB = sa0 + st * TILEB;
        const uint32_t bB = sb0 + st * TILEB;
        #pragma unroll
        for (int ks = 0; ks < 64; ks += 16) {
            uint32_t af[2][4], bfr[4][4];
            #pragma unroll
            for (int mt = 0; mt < 2; mt++) {
                uint32_t addr = aB + (m0 + mt * 16 + (lane & 15)) * ROWB
                              + (ks + ((lane >> 4) << 3)) * 2;
                LDMX4(af[mt], addr);
            }
            #pragma unroll
            for (int nt = 0; nt < 4; nt++) {
                uint32_t addr = bB + (n0w + nt * 16 + (lane & 7) + ((lane & 16) >> 1)) * ROWB
                              + (ks + (((lane >> 3) & 1) << 3)) * 2;
                LDMX4(bfr[nt], addr);
            }
            #pragma unroll
            for (int mt = 0; mt < 2; mt++)
                #pragma unroll
                for (int nt = 0; nt < 4; nt++) {
                    MMA16816(acc[mt][2 * nt],     af[mt], bfr[nt][0], bfr[nt][1]);
                    MMA16816(acc[mt][2 * nt + 1], af[mt], bfr[nt][2], bfr[nt][3]);
                }
        }
    }

    // ---- epilogue: process + stage into smem ----
    __syncthreads();                       // mainloop fully done; smem reusable
    bf16* sd = (bf16*)smem;                // staging tile 128 x SPITCH bf16
    const int lr_base = m0 + (lane >> 2);  // CTA-local row
    const int c_loc0 = n0w + (lane & 3) * 2;
    const bool v_trans = (EPI == 0 && by >= 4);
    float sumA[2] = {0.f, 0.f};
    float sumB[2] = {0.f, 0.f};

    #pragma unroll
    for (int mt = 0; mt < 2; mt++) {
        #pragma unroll
        for (int nj = 0; nj < 8; nj++) {
            float* d = acc[mt][nj];
            const int lr0 = lr_base + mt * 16;
            const int c   = c_loc0 + nj * 8;
            float p00, p01, p10, p11;

            if (EPI == 0) {
                int gc = by * 128 + c;
                float bi0 = g_bs[gc], bi1 = g_bs[gc + 1];
                if (gc < 256) {                       // Q: fold in SCALE_QK
                    p00 = (d[0] + bi0) * SCALE_QK; p01 = (d[1] + bi1) * SCALE_QK;
                    p10 = (d[2] + bi0) * SCALE_QK; p11 = (d[3] + bi1) * SCALE_QK;
                } else {
                    p00 = d[0] + bi0; p01 = d[1] + bi1;
                    p10 = d[2] + bi0; p11 = d[3] + bi1;
                }
            } else if (EPI == 1) {
                // P = exp(logit) (no max subtraction; logits bounded, fp32/bf16 safe)
                p00 = __expf(d[0]); p01 = __expf(d[1]);
                p10 = __expf(d[2]); p11 = __expf(d[3]);
                sumA[mt] += p00 + p01;
                sumB[mt] += p10 + p11;
            } else {
                p00 = d[0]; p01 = d[1]; p10 = d[2]; p11 = d[3];
            }

            if (!v_trans) {
                *(__nv_bfloat162*)&sd[lr0 * SPITCH + c] =
                    __float22bfloat162_rn(make_float2(p00, p01));
                *(__nv_bfloat162*)&sd[(lr0 + 8) * SPITCH + c] =
                    __float22bfloat162_rn(make_float2(p10, p11));
            } else {                       // V: stage transposed (cc-major rows)
                sd[c * SPITCH + lr0]           = __float2bfloat16(p00);
                sd[(c + 1) * SPITCH + lr0]     = __float2bfloat16(p01);
                sd[c * SPITCH + lr0 + 8]       = __float2bfloat16(p10);
                sd[(c + 1) * SPITCH + lr0 + 8] = __float2bfloat16(p11);
            }
        }
    }

    if (EPI == 1) {
        #pragma unroll
        for (int mt = 0; mt < 2; mt++) {
            float sA = sumA[mt], sB = sumB[mt];
            sA += __shfl_xor_sync(0xFFFFFFFF, sA, 1);
            sA += __shfl_xor_sync(0xFFFFFFFF, sA, 2);
            sB += __shfl_xor_sync(0xFFFFFFFF, sB, 1);
            sB += __shfl_xor_sync(0xFFFFFFFF, sB, 2);
            if ((lane & 3) == 0) {
                int row = bx * 128 + lr_base + mt * 16;
                atomicAdd(&g_rs[(size_t)bz * NTOK + row], sA);
                atomicAdd(&g_rs[(size_t)bz * NTOK + row + 8], sB);
            }
        }
    }
    __syncthreads();                       // staging complete

    // ---- coalesced write-out: 128 rows x 256B, 16B per thread-iteration ----
    #pragma unroll
    for (int it = tid; it < 2048; it += 256) {
        int row = it >> 4;                 // staged row (token, or cc for V)
        int ch  = (it & 15) * 8;           // bf16 column offset (16B chunks)
        uint4 v = *(uint4*)&sd[row * SPITCH + ch];
        if (EPI == 0) {
            if (by < 2)
                *(uint4*)&g_qt[(size_t)(bx * 128 + row) * CC + (by & 1) * 128 + ch] = v;
            else if (by < 4)
                *(uint4*)&g_kt[(size_t)(bx * 128 + row) * CC + ((by - 2) & 1) * 128 + ch] = v;
            else
                *(uint4*)&g_vp[(size_t)((by - 4) * 128 + row) * BNC + bx * 128 + ch] = v;
        } else if (EPI == 1) {
            bf16* L = g_attn + (size_t)bz * NN;
            *(uint4*)&L[(size_t)(bx * 128 + row) * NTOK + by * 128 + ch] = v;
        } else {
            const int b = bz >> 1, ks = bz & 1;
            bf16* O = (ks ? g_o2 : g_o) + (size_t)b * NTOK * CC;
            *(uint4*)&O[(size_t)(bx * 128 + row) * CC + by * 128 + ch] = v;
        }
    }
}

// ---------------- prep: BN stats (blocks 0..127) + weight stacking + zero ---
__global__ __launch_bounds__(256) void prep_kernel(
    const float* __restrict__ x,
    const float* __restrict__ bn_w, const float* __restrict__ bn_b,
    const float* __restrict__ wq, const float* __restrict__ bq,
    const float* __restrict__ wk, const float* __restrict__ bk,
    const float* __restrict__ wv, const float* __restrict__ bv) {
    if (blockIdx.x < CH) {
        int c = blockIdx.x;
        float sr = 0.f, si = 0.f, qr = 0.f, qi = 0.f;
        #pragma unroll
        for (int b = 0; b < BB; b++) {
            const float4* p = (const float4*)x + (size_t)(b * CH + c) * (HWN / 2);
            for (int i = threadIdx.x; i < HWN / 2; i += 256) {
                float4 v = p[i];
                sr += v.x + v.z;  si += v.y + v.w;
                qr += v.x * v.x + v.z * v.z;
                qi += v.y * v.y + v.w * v.w;
            }
        }
        #pragma unroll
        for (int o = 16; o > 0; o >>= 1) {
            sr += __shfl_xor_sync(0xFFFFFFFF, sr, o);
            si += __shfl_xor_sync(0xFFFFFFFF, si, o);
            qr += __shfl_xor_sync(0xFFFFFFFF, qr, o);
            qi += __shfl_xor_sync(0xFFFFFFFF, qi, o);
        }
        __shared__ float s4[4][8];
        int wid = threadIdx.x >> 5, lane = threadIdx.x & 31;
        if (lane == 0) { s4[0][wid] = sr; s4[1][wid] = si; s4[2][wid] = qr; s4[3][wid] = qi; }
        __syncthreads();
        if (threadIdx.x == 0) {
            float tsr = 0, tsi = 0, tqr = 0, tqi = 0;
            #pragma unroll
            for (int w = 0; w < 8; w++) { tsr += s4[0][w]; tsi += s4[1][w]; tqr += s4[2][w]; tqi += s4[3][w]; }
            const float inv = 1.f / (float)(BB * HWN);
            float mr = tsr * inv, mi = tsi * inv;
            float vr = tqr * inv - mr * mr, vi = tqi * inv - mi * mi;
            float scr = bn_w[c * 2 + 0] * rsqrtf(vr + EPSV);
            float sci = bn_w[c * 2 + 1] * rsqrtf(vi + EPSV);
            g_scale[c]      = scr;  g_shift[c]      = bn_b[c * 2 + 0] - mr * scr;
            g_scale[CH + c] = sci;  g_shift[CH + c] = bn_b[c * 2 + 1] - mi * sci;
        }
    } else {
        int idx = (blockIdx.x - CH) * 256 + threadIdx.x;   // 0 .. 3*128*128-1
        int p = idx / (CH * CH);
        int r = idx - p * (CH * CH);
        int o = r / CH, i = r % CH;
        const float* w = (p == 0) ? wq : ((p == 1) ? wk : wv);
        float wr = w[(o * CH + i) * 2 + 0];
        float wi = w[(o * CH + i) * 2 + 1];
        bf16* ws = g_ws_bf + (size_t)p * CC * CC;
        ws[o * CC + i]             = __float2bfloat16( wr);
        ws[o * CC + CH + i]        = __float2bfloat16(-wi);
        ws[(CH + o) * CC + i]      = __float2bfloat16( wi);
        ws[(CH + o) * CC + CH + i] = __float2bfloat16( wr);
        if (i == 0) {
            const float* bbp = (p == 0) ? bq : ((p == 1) ? bk : bv);
            g_bs[p * CC + o]      = bbp[o * 2 + 0];
            g_bs[p * CC + CH + o] = bbp[o * 2 + 1];
        }
        int zb = blockIdx.x - CH;
        if (zb < 32) g_rs[zb * 256 + threadIdx.x] = 0.f;
    }
}

// ---------------- normalize: token-major bf16 only ---------------------------
__global__ void normalize_kernel(const float* __restrict__ x) {
    __shared__ float shr[32][33];
    __shared__ float shi[32][33];
    int b  = blockIdx.z;
    int c0 = blockIdx.y * 32;
    int n0 = blockIdx.x * 32;
    int tx = threadIdx.x, ty = threadIdx.y;
    int c = c0 + ty, n = n0 + tx;
    float2 v = ((const float2*)x)[(size_t)(b * CH + c) * HWN + n];
    shr[ty][tx] = v.x * g_scale[c]      + g_shift[c];
    shi[ty][tx] = v.y * g_scale[CH + c] + g_shift[CH + c];
    __syncthreads();
    int token = n0 + ty;
    int cw = c0 + (tx & 15) * 2;
    bf16* dst = g_xt + ((size_t)b * NTOK + token) * CC;
    if (tx < 16) {
        *(__nv_bfloat162*)&dst[cw] =
            __float22bfloat162_rn(make_float2(shr[(tx & 15) * 2][ty], shr[(tx & 15) * 2 + 1][ty]));
    } else {
        *(__nv_bfloat162*)&dst[CH + cw] =
            __float22bfloat162_rn(make_float2(shi[(tx & 15) * 2][ty], shi[(tx & 15) * 2 + 1][ty]));
    }
}

// ---------------- residual add (xn recomputed) + rowsum norm + split-K ------
__global__ void final_add_kernel(const float* __restrict__ x,
                                 const float* __restrict__ gamma_p,
                                 float* __restrict__ out) {
    __shared__ float shr[32][33];
    __shared__ float shi[32][33];
    float gamma = *gamma_p;
    int b  = blockIdx.z;
    int c0 = blockIdx.y * 32;
    int n0 = blockIdx.x * 32;
    int tx = threadIdx.x, ty = threadIdx.y;
    size_t obase = ((size_t)b * NTOK + n0 + ty) * CC;
    {
        float pr = __bfloat162float(g_o [obase + c0 + tx]) +
                   __bfloat162float(g_o2[obase + c0 + tx]);
        float pi = __bfloat162float(g_o [obase + CH + c0 + tx]) +
                   __bfloat162float(g_o2[obase + CH + c0 + tx]);
        shr[ty][tx] = pr; shi[ty][tx] = pi;
    }
    __syncthreads();
    int c = c0 + ty;
    int n = n0 + tx;
    size_t col = (size_t)b * NTOK + n;
    float inv = gamma / g_rs[col];
    size_t oi = (size_t)(b * CH + c) * HWN + n;
    float2 xv = ((const float2*)x)[oi];
    float xr = xv.x * g_scale[c]      + g_shift[c];
    float xi = xv.y * g_scale[CH + c] + g_shift[CH + c];
    float2 ov;
    ov.x = xr + inv * shr[tx][ty];
    ov.y = xi + inv * shi[tx][ty];
    ((float2*)out)[oi] = ov;
}

// ---------------- launch -----------------------------------------------------
extern "C" void kernel_launch(void* const* d_in, const int* in_sizes, int n_in,
                              void* d_out, int out_size) {
    const float* x    = (const float*)d_in[0];
    const float* bn_w = (const float*)d_in[1];
    const float* bn_b = (const float*)d_in[2];
    const float* wq   = (const float*)d_in[3];
    const float* bq   = (const float*)d_in[4];
    const float* wk   = (const float*)d_in[5];
    const float* bk   = (const float*)d_in[6];
    const float* wv   = (const float*)d_in[7];
    const float* bv   = (const float*)d_in[8];
    const float* gam  = (const float*)d_in[9];
    float* out = (float*)d_out;

    static int attr_set = 0;
    if (!attr_set) {
        cudaFuncSetAttribute((const void*)gemm_kernel<0, 4>,  cudaFuncAttributeMaxDynamicSharedMemorySize, SM_TOTAL);
        cudaFuncSetAttribute((const void*)gemm_kernel<1, 4>,  cudaFuncAttributeMaxDynamicSharedMemorySize, SM_TOTAL);
        cudaFuncSetAttribute((const void*)gemm_kernel<2, 32>, cudaFuncAttributeMaxDynamicSharedMemorySize, SM_TOTAL);
        attr_set = 1;
    }

    prep_kernel<<<CH + 192, 256>>>(x, bn_w, bn_b, wq, bq, wk, bk, wv, bv);
    normalize_kernel<<<dim3(HWN / 32, CH / 32, BB), dim3(32, 32)>>>(x);
    gemm_kernel<0, 4><<<dim3(BNC / 128, 6), 256, SM_TOTAL>>>();
    gemm_kernel<1, 4><<<dim3(NTOK / 128, NTOK / 128, BB), 256, SM_TOTAL>>>();
    gemm_kernel<2, 32><<<dim3(NTOK / 128, CC / 128, BB * 2), 256, SM_TOTAL>>>();
    final_add_kernel<<<dim3(HWN / 32, CH / 32, BB), dim3(32, 32)>>>(x, gam, out);
}